// round 15
// baseline (speedup 1.0000x reference)
#include <cuda_runtime.h>
#include <cuda_bf16.h>
#include <cstdint>
#include <math.h>

// Problem constants
#define BB 4
#define LL 2048
#define DD 1024
#define HH 16
#define DK 64
#define MTOT (BB*LL)          // 8192

// ---------------- scratch (device globals; no allocation allowed) ------------
__device__ float  g_qp[BB*LL*DD];     // qpT [1024, 8192]
__device__ float  g_kp[BB*LL*DD];     // kpT [1024, 8192]
__device__ float  g_vp[BB*LL*DD];     // vp natural [8192, 1024]
__device__ float  g_Mf[BB*DD];        // fp32 per-channel max autocorr
__device__ double g_Md[BB*DD];        // DP rescue values (flagged heads only)
__device__ int    g_flag[BB*HH];      // per-head "borderline" flag
__device__ int    g_shift[BB*DD];
__device__ double2 g_tw[1024];        // DP twiddles exp(-2*pi*i*j/2048)
__device__ float2  g_twf[1024];       // fp32 twiddles
// bf16 split scratch: 3 activation slots, 4 weight slots
__device__ __nv_bfloat16 g_Ah[3ULL*MTOT*DD];
__device__ __nv_bfloat16 g_Al[3ULL*MTOT*DD];
__device__ __nv_bfloat16 g_WhT[4ULL*DD*DD];
__device__ __nv_bfloat16 g_WlT[4ULL*DD*DD];

// ============================ PTX helpers =====================================
__device__ __forceinline__ uint32_t smem_u32(const void* p) {
    uint32_t a;
    asm("{ .reg .u64 t; cvta.to.shared.u64 t, %1; cvt.u32.u64 %0, t; }"
        : "=r"(a) : "l"(p));
    return a;
}
__device__ __forceinline__ void cp16(uint32_t dst, const void* src) {
    asm volatile("cp.async.cg.shared.global [%0], [%1], 16;\n" :: "r"(dst), "l"(src));
}
#define CP_COMMIT() asm volatile("cp.async.commit_group;" ::: "memory")

__device__ __forceinline__ void ldsm4(uint32_t (&r)[4], uint32_t addr) {
    asm volatile("ldmatrix.sync.aligned.m8n8.x4.shared.b16 {%0,%1,%2,%3}, [%4];"
        : "=r"(r[0]), "=r"(r[1]), "=r"(r[2]), "=r"(r[3]) : "r"(addr));
}
__device__ __forceinline__ void mma_bf16(float (&d)[4], const uint32_t (&a)[4],
                                         uint32_t b0, uint32_t b1) {
    asm volatile("mma.sync.aligned.m16n8k16.row.col.f32.bf16.bf16.f32 "
        "{%0,%1,%2,%3}, {%4,%5,%6,%7}, {%8,%9}, {%0,%1,%2,%3};"
        : "+f"(d[0]), "+f"(d[1]), "+f"(d[2]), "+f"(d[3])
        : "r"(a[0]), "r"(a[1]), "r"(a[2]), "r"(a[3]), "r"(b0), "r"(b1));
}

// ==================== mma.sync bf16-split GEMM (batched) ======================
#define BK 32
#define NKITER (DD / BK)      // 32
#define SMAT (128 * 64)       // 8192 bytes per matrix tile
#define SSTAGE (4 * SMAT)     // 32768
#define NSTAGE 3
#define GSMEM_TOTAL (NSTAGE * SSTAGE)   // 98304

#define SWZ(r, c) ((c) ^ ((r) & 3) ^ (((r) >> 2) & 1))

struct GemmArgs {
    const __nv_bfloat16 *Ah, *Al, *Bh, *Bl;
    const float* bias;
    float* C;
    int cstride;
    int rowbias;   // 1: T-orientation (m0 from blockIdx.y, bias[m]); 0: normal
};
struct GemmArgs3 { GemmArgs g[3]; };

__global__ __launch_bounds__(256) void gemm_mma_kernel(GemmArgs3 args)
{
    const GemmArgs a = args.g[blockIdx.z];
    extern __shared__ __align__(128) char smem[];
    const uint32_t sb = smem_u32(smem);
    const int tid = threadIdx.x;
    const int wid = tid >> 5;
    const int lane = tid & 31;
    const int m0 = (a.rowbias ? blockIdx.y : blockIdx.x) << 7;
    const int n0 = (a.rowbias ? blockIdx.x : blockIdx.y) << 7;
    const int mw = (wid >> 2) << 6;
    const int nw = (wid & 3) << 5;

    float acc[4][4][4];
    #pragma unroll
    for (int mt = 0; mt < 4; mt++)
        #pragma unroll
        for (int nt = 0; nt < 4; nt++)
            #pragma unroll
            for (int e = 0; e < 4; e++) acc[mt][nt][e] = 0.f;

    auto issue = [&](int kb, int s) {
        const uint32_t base = sb + s * SSTAGE;
        const int k0 = kb * BK;
        #pragma unroll
        for (int i = 0; i < 2; i++) {
            int e = tid + (i << 8);
            int r = e >> 2;
            int c = e & 3;
            uint32_t doff = (uint32_t)(r * 64 + SWZ(r, c) * 16);
            const char* pa = (const char*)(a.Ah + (size_t)(m0 + r) * DD + k0) + c * 16;
            const char* pl = (const char*)(a.Al + (size_t)(m0 + r) * DD + k0) + c * 16;
            const char* pb = (const char*)(a.Bh + (size_t)(n0 + r) * DD + k0) + c * 16;
            const char* pq = (const char*)(a.Bl + (size_t)(n0 + r) * DD + k0) + c * 16;
            cp16(base + 0 * SMAT + doff, pa);
            cp16(base + 1 * SMAT + doff, pl);
            cp16(base + 2 * SMAT + doff, pb);
            cp16(base + 3 * SMAT + doff, pq);
        }
        CP_COMMIT();
    };

    issue(0, 0);
    issue(1, 1);

    for (int kb = 0; kb < NKITER; kb++) {
        if (kb == NKITER - 1) asm volatile("cp.async.wait_group 0;" ::: "memory");
        else                  asm volatile("cp.async.wait_group 1;" ::: "memory");
        __syncthreads();
        if (kb + 2 < NKITER) issue(kb + 2, (kb + 2) % NSTAGE);

        const uint32_t base = sb + (kb % NSTAGE) * SSTAGE;
        #pragma unroll
        for (int ks = 0; ks < 2; ks++) {
            uint32_t ah[4][4], al[4][4];
            #pragma unroll
            for (int mt = 0; mt < 4; mt++) {
                int row = mw + (mt << 4) + (lane & 15);
                int cc = ks * 2 + (lane >> 4);
                uint32_t addr = base + (uint32_t)(row * 64 + SWZ(row, cc) * 16);
                ldsm4(ah[mt], addr);
                ldsm4(al[mt], addr + SMAT);
            }
            uint32_t bh[2][4], bl[2][4];
            #pragma unroll
            for (int p = 0; p < 2; p++) {
                int nrow = nw + (p << 4) + (lane & 7) + (((lane >> 4) & 1) << 3);
                int cc = ks * 2 + ((lane >> 3) & 1);
                uint32_t addr = base + 2 * SMAT
                              + (uint32_t)(nrow * 64 + SWZ(nrow, cc) * 16);
                ldsm4(bh[p], addr);
                ldsm4(bl[p], addr + SMAT);
            }
            #pragma unroll
            for (int mt = 0; mt < 4; mt++)
                #pragma unroll
                for (int nt = 0; nt < 4; nt++) {
                    uint32_t h0 = bh[nt >> 1][(nt & 1) * 2];
                    uint32_t h1 = bh[nt >> 1][(nt & 1) * 2 + 1];
                    uint32_t l0 = bl[nt >> 1][(nt & 1) * 2];
                    uint32_t l1 = bl[nt >> 1][(nt & 1) * 2 + 1];
                    mma_bf16(acc[mt][nt], ah[mt], h0, h1);
                    mma_bf16(acc[mt][nt], ah[mt], l0, l1);
                    mma_bf16(acc[mt][nt], al[mt], h0, h1);
                }
        }
    }

    #pragma unroll
    for (int mt = 0; mt < 4; mt++) {
        #pragma unroll
        for (int nt = 0; nt < 4; nt++) {
            int m = m0 + mw + (mt << 4) + (lane >> 2);
            int n = n0 + nw + (nt << 3) + ((lane & 3) << 1);
            float2 v0, v1;
            if (a.rowbias) {
                float bm0 = a.bias[m], bm1 = a.bias[m + 8];
                v0 = make_float2(acc[mt][nt][0] + bm0, acc[mt][nt][1] + bm0);
                v1 = make_float2(acc[mt][nt][2] + bm1, acc[mt][nt][3] + bm1);
            } else {
                float b0 = a.bias[n], b1 = a.bias[n + 1];
                v0 = make_float2(acc[mt][nt][0] + b0, acc[mt][nt][1] + b1);
                v1 = make_float2(acc[mt][nt][2] + b0, acc[mt][nt][3] + b1);
            }
            *(float2*)(a.C + (size_t)m * a.cstride + n) = v0;
            *(float2*)(a.C + (size_t)(m + 8) * a.cstride + n) = v1;
        }
    }
}

// ==================== fp32 -> bf16 hi/lo converters (batched) =================
struct ConvA3 {
    const float4* src[3];
    __nv_bfloat162* h[3];
    __nv_bfloat162* l[3];
};
__global__ void convA3_kernel(ConvA3 p)
{
    const int z = blockIdx.z;
    int i = blockIdx.x * blockDim.x + threadIdx.x;
    float4 v = p.src[z][i];
    __nv_bfloat16 h0 = __float2bfloat16(v.x);
    __nv_bfloat16 h1 = __float2bfloat16(v.y);
    __nv_bfloat16 h2 = __float2bfloat16(v.z);
    __nv_bfloat16 h3 = __float2bfloat16(v.w);
    p.h[z][2 * i + 0] = __halves2bfloat162(h0, h1);
    p.h[z][2 * i + 1] = __halves2bfloat162(h2, h3);
    p.l[z][2 * i + 0] = __halves2bfloat162(
        __float2bfloat16(v.x - __bfloat162float(h0)),
        __float2bfloat16(v.y - __bfloat162float(h1)));
    p.l[z][2 * i + 1] = __halves2bfloat162(
        __float2bfloat16(v.z - __bfloat162float(h2)),
        __float2bfloat16(v.w - __bfloat162float(h3)));
}

// fused: roll vp by per-(b,c) shift (0/1) while converting to bf16 hi/lo
__global__ void convA_shift_kernel(const float* __restrict__ vp,
                                   const int* __restrict__ shifts,
                                   __nv_bfloat162* __restrict__ Ah2,
                                   __nv_bfloat162* __restrict__ Al2)
{
    int i = blockIdx.x * blockDim.x + threadIdx.x;
    int c4 = (i & 255) << 2;
    int t = (i >> 8) & 2047;
    int b = i >> 19;
    const int sbase = (b << 10) + c4;
    float v[4];
    #pragma unroll
    for (int j = 0; j < 4; j++) {
        int s = shifts[sbase + j];
        int t2 = (t - s) & 2047;
        v[j] = vp[((size_t)((b << 11) + t2) << 10) + c4 + j];
    }
    __nv_bfloat16 h0 = __float2bfloat16(v[0]);
    __nv_bfloat16 h1 = __float2bfloat16(v[1]);
    __nv_bfloat16 h2 = __float2bfloat16(v[2]);
    __nv_bfloat16 h3 = __float2bfloat16(v[3]);
    Ah2[2 * i + 0] = __halves2bfloat162(h0, h1);
    Ah2[2 * i + 1] = __halves2bfloat162(h2, h3);
    Al2[2 * i + 0] = __halves2bfloat162(
        __float2bfloat16(v[0] - __bfloat162float(h0)),
        __float2bfloat16(v[1] - __bfloat162float(h1)));
    Al2[2 * i + 1] = __halves2bfloat162(
        __float2bfloat16(v[2] - __bfloat162float(h2)),
        __float2bfloat16(v[3] - __bfloat162float(h3)));
}

struct ConvW4 {
    const float* W[4];
    __nv_bfloat16* h[4];
    __nv_bfloat16* l[4];
};
__global__ void convWT4_kernel(ConvW4 p)
{
    __shared__ float t[32][33];
    const int z = blockIdx.z;
    const int tx = threadIdx.x, ty = threadIdx.y;
    const int kb = blockIdx.y * 32, nb = blockIdx.x * 32;
    #pragma unroll
    for (int j = 0; j < 32; j += 8)
        t[ty + j][tx] = p.W[z][(size_t)(kb + ty + j) * DD + nb + tx];
    __syncthreads();
    #pragma unroll
    for (int j = 0; j < 32; j += 8) {
        float v = t[tx][ty + j];
        __nv_bfloat16 h = __float2bfloat16(v);
        p.h[z][(size_t)(nb + ty + j) * DD + kb + tx] = h;
        p.l[z][(size_t)(nb + ty + j) * DD + kb + tx] =
            __float2bfloat16(v - __bfloat162float(h));
    }
}

// ======================= twiddle init (DP + fp32) =============================
__global__ void twiddle_init_kernel() {
    int j = blockIdx.x * blockDim.x + threadIdx.x;
    if (j < 1024) {
        double ang = -6.283185307179586476925286766559 * (double)j / 2048.0;
        double s, c;
        sincos(ang, &s, &c);
        g_tw[j] = make_double2(c, s);
        g_twf[j] = make_float2((float)c, (float)s);
    }
}

// ===== Stockham DIF FFT autocorrelation (fp32 fast path + DP rescue) ==========
#define FFT_N 2048
#define AC_T 256
#define AC_SMEM_D (3 * FFT_N * 16)   // 98304 bytes (DP)
#define AC_SMEM_F (3 * FFT_N * 8)    // 49152 bytes (fp32)

__device__ __forceinline__ double2* fft11d(double2* x, double2* y, int tid) {
    double2* src = x;
    double2* dst = y;
    #pragma unroll
    for (int t = 0; t < 11; t++) {
        const int s = 1 << t;
        for (int j = tid; j < FFT_N / 2; j += AC_T) {
            int q = j & (s - 1);
            int ps = (j >> t) << t;
            double2 a = src[q + ps];
            double2 b = src[q + ps + FFT_N / 2];
            double2 w = g_tw[ps];
            double sx = a.x - b.x, sy = a.y - b.y;
            dst[q + 2 * ps]     = make_double2(a.x + b.x, a.y + b.y);
            dst[q + 2 * ps + s] = make_double2(sx * w.x - sy * w.y,
                                               sx * w.y + sy * w.x);
        }
        __syncthreads();
        double2* tmp = src; src = dst; dst = tmp;
    }
    return src;
}

__device__ __forceinline__ float2* fft11f(float2* x, float2* y, int tid) {
    float2* src = x;
    float2* dst = y;
    #pragma unroll
    for (int t = 0; t < 11; t++) {
        const int s = 1 << t;
        for (int j = tid; j < FFT_N / 2; j += AC_T) {
            int q = j & (s - 1);
            int ps = (j >> t) << t;
            float2 a = src[q + ps];
            float2 b = src[q + ps + FFT_N / 2];
            float2 w = g_twf[ps];
            float sx = a.x - b.x, sy = a.y - b.y;
            dst[q + 2 * ps]     = make_float2(a.x + b.x, a.y + b.y);
            dst[q + 2 * ps + s] = make_float2(sx * w.x - sy * w.y,
                                              sx * w.y + sy * w.x);
        }
        __syncthreads();
        float2* tmp = src; src = dst; dst = tmp;
    }
    return src;
}

__global__ __launch_bounds__(AC_T) void autocorr_f32_kernel(
    const float* __restrict__ qpT, const float* __restrict__ kpT,
    float* __restrict__ Mout)
{
    extern __shared__ float2 sbf[];
    float2* B0 = sbf;
    float2* B1 = sbf + FFT_N;
    float2* BC = sbf + 2 * FFT_N;
    __shared__ float red[16];

    const int tid = threadIdx.x;
    const int ch0 = blockIdx.x * 2;
    const int ch1 = ch0 + 1;
    const size_t a0 = (size_t)(ch0 & 1023) * 8192 + (size_t)(ch0 >> 10) * 2048;
    const size_t a1 = (size_t)(ch1 & 1023) * 8192 + (size_t)(ch1 >> 10) * 2048;

    for (int i = tid; i < FFT_N; i += AC_T)
        B0[i] = make_float2(qpT[a0 + i], kpT[a0 + i]);
    __syncthreads();
    float2* Z = fft11f(B0, B1, tid);

    for (int f = tid; f <= FFT_N / 2; f += AC_T) {
        int f2 = (FFT_N - f) & (FFT_N - 1);
        float2 z1 = Z[f];
        float2 z2 = Z[f2];
        float2 fq = make_float2(0.5f * (z1.x + z2.x), 0.5f * (z1.y - z2.y));
        float2 fk = make_float2(0.5f * (z1.y + z2.y), -0.5f * (z1.x - z2.x));
        float gx = fq.x * fk.x + fq.y * fk.y;
        float gy = fq.y * fk.x - fq.x * fk.y;
        BC[f]  = make_float2(gx, -gy);
        BC[f2] = make_float2(gx,  gy);
    }
    for (int i = tid; i < FFT_N; i += AC_T)
        B0[i] = make_float2(qpT[a1 + i], kpT[a1 + i]);
    __syncthreads();
    Z = fft11f(B0, B1, tid);

    for (int f = tid; f <= FFT_N / 2; f += AC_T) {
        int f2 = (FFT_N - f) & (FFT_N - 1);
        float2 z1 = Z[f];
        float2 z2 = Z[f2];
        float2 fq = make_float2(0.5f * (z1.x + z2.x), 0.5f * (z1.y - z2.y));
        float2 fk = make_float2(0.5f * (z1.y + z2.y), -0.5f * (z1.x - z2.x));
        float gx = fq.x * fk.x + fq.y * fk.y;
        float gy = fq.y * fk.x - fq.x * fk.y;
        float2 c0 = BC[f];
        float2 c2 = BC[f2];
        B0[f]  = make_float2(c0.x - gy, c0.y - gx);
        B0[f2] = make_float2(c2.x + gy, c2.y - gx);
    }
    __syncthreads();
    float2* Y = fft11f(B0, B1, tid);

    float m0 = -3.0e38f, m1 = -3.0e38f;
    for (int i = tid; i < FFT_N; i += AC_T) {
        if (i != 0) {
            float2 y = Y[i];
            m0 = fmaxf(m0, y.x);
            m1 = fmaxf(m1, -y.y);
        }
    }
    #pragma unroll
    for (int off = 16; off > 0; off >>= 1) {
        m0 = fmaxf(m0, __shfl_xor_sync(0xffffffffu, m0, off));
        m1 = fmaxf(m1, __shfl_xor_sync(0xffffffffu, m1, off));
    }
    if ((tid & 31) == 0) { red[tid >> 5] = m0; red[8 + (tid >> 5)] = m1; }
    __syncthreads();
    if (tid == 0) {
        float r0 = red[0], r1 = red[8];
        #pragma unroll
        for (int w = 1; w < AC_T / 32; w++) {
            r0 = fmaxf(r0, red[w]);
            r1 = fmaxf(r1, red[8 + w]);
        }
        Mout[ch0] = r0 * (1.0f / FFT_N);
        Mout[ch1] = r1 * (1.0f / FFT_N);
    }
}

__global__ __launch_bounds__(AC_T) void autocorr_dp_kernel(
    const float* __restrict__ qpT, const float* __restrict__ kpT,
    const int* __restrict__ flag, double* __restrict__ Mout)
{
    const int ch0 = blockIdx.x * 2;
    if (flag[ch0 >> 6] == 0) return;

    extern __shared__ double2 sbd[];
    double2* B0 = sbd;
    double2* B1 = sbd + FFT_N;
    double2* BC = sbd + 2 * FFT_N;
    __shared__ double red[16];

    const int tid = threadIdx.x;
    const int ch1 = ch0 + 1;
    const size_t a0 = (size_t)(ch0 & 1023) * 8192 + (size_t)(ch0 >> 10) * 2048;
    const size_t a1 = (size_t)(ch1 & 1023) * 8192 + (size_t)(ch1 >> 10) * 2048;

    for (int i = tid; i < FFT_N; i += AC_T)
        B0[i] = make_double2((double)qpT[a0 + i], (double)kpT[a0 + i]);
    __syncthreads();
    double2* Z = fft11d(B0, B1, tid);

    for (int f = tid; f <= FFT_N / 2; f += AC_T) {
        int f2 = (FFT_N - f) & (FFT_N - 1);
        double2 z1 = Z[f];
        double2 z2 = Z[f2];
        double2 fq = make_double2(0.5 * (z1.x + z2.x), 0.5 * (z1.y - z2.y));
        double2 fk = make_double2(0.5 * (z1.y + z2.y), -0.5 * (z1.x - z2.x));
        double gx = fq.x * fk.x + fq.y * fk.y;
        double gy = fq.y * fk.x - fq.x * fk.y;
        BC[f]  = make_double2(gx, -gy);
        BC[f2] = make_double2(gx,  gy);
    }
    for (int i = tid; i < FFT_N; i += AC_T)
        B0[i] = make_double2((double)qpT[a1 + i], (double)kpT[a1 + i]);
    __syncthreads();
    Z = fft11d(B0, B1, tid);

    for (int f = tid; f <= FFT_N / 2; f += AC_T) {
        int f2 = (FFT_N - f) & (FFT_N - 1);
        double2 z1 = Z[f];
        double2 z2 = Z[f2];
        double2 fq = make_double2(0.5 * (z1.x + z2.x), 0.5 * (z1.y - z2.y));
        double2 fk = make_double2(0.5 * (z1.y + z2.y), -0.5 * (z1.x - z2.x));
        double gx = fq.x * fk.x + fq.y * fk.y;
        double gy = fq.y * fk.x - fq.x * fk.y;
        double2 c0 = BC[f];
        double2 c2 = BC[f2];
        B0[f]  = make_double2(c0.x - gy, c0.y - gx);
        B0[f2] = make_double2(c2.x + gy, c2.y - gx);
    }
    __syncthreads();
    double2* Y = fft11d(B0, B1, tid);

    double m0 = -1.0e300, m1 = -1.0e300;
    for (int i = tid; i < FFT_N; i += AC_T) {
        if (i != 0) {
            double2 y = Y[i];
            m0 = fmax(m0, y.x);
            m1 = fmax(m1, -y.y);
        }
    }
    #pragma unroll
    for (int off = 16; off > 0; off >>= 1) {
        m0 = fmax(m0, __shfl_xor_sync(0xffffffffu, m0, off));
        m1 = fmax(m1, __shfl_xor_sync(0xffffffffu, m1, off));
    }
    if ((tid & 31) == 0) { red[tid >> 5] = m0; red[8 + (tid >> 5)] = m1; }
    __syncthreads();
    if (tid == 0) {
        double r0 = red[0], r1 = red[8];
        #pragma unroll
        for (int w = 1; w < AC_T / 32; w++) {
            r0 = fmax(r0, red[w]);
            r1 = fmax(r1, red[8 + w]);
        }
        Mout[ch0] = r0 * (1.0 / FFT_N);
        Mout[ch1] = r1 * (1.0 / FFT_N);
    }
}

// ===== per-head fp32 softmax + shifts + borderline flag =======================
__global__ void flag_softmax_kernel(const float* __restrict__ Mf,
                                    int* __restrict__ shifts,
                                    int* __restrict__ flag)
{
    const int bh = blockIdx.x;
    const int base = ((bh >> 4) << 10) + ((bh & 15) << 6);
    if (threadIdx.x == 0) {
        float x[DK];
        float mx = -3.4e38f;
        int amax = 0;
        for (int c = 0; c < DK; c++) {
            x[c] = Mf[base + c];
            if (x[c] > mx) { mx = x[c]; amax = c; }
        }
        float e[DK];
        float s = 0.f;
        for (int c = 0; c < DK; c++) {
            e[c] = expf(x[c] - mx);
            s += e[c];
        }
        for (int c = 0; c < DK; c++)
            shifts[base + c] = (int)(e[c] / s);
        double rest = 0.0;
        for (int c = 0; c < DK; c++)
            if (c != amax) rest += exp((double)x[c] - (double)mx);
        double l2 = log2(rest);
        flag[bh] = (fabs(l2 + 24.0) < 0.5) ? 1 : 0;
    }
}

__global__ void softmax_fix_kernel(const double* __restrict__ Md,
                                   const int* __restrict__ flag,
                                   int* __restrict__ shifts)
{
    const int bh = blockIdx.x;
    if (flag[bh] == 0) return;
    const int base = ((bh >> 4) << 10) + ((bh & 15) << 6);
    if (threadIdx.x == 0) {
        float x[DK];
        float mx = -3.4e38f;
        for (int c = 0; c < DK; c++) {
            x[c] = (float)Md[base + c];
            mx = fmaxf(mx, x[c]);
        }
        float e[DK];
        float s = 0.f;
        for (int c = 0; c < DK; c++) {
            e[c] = expf(x[c] - mx);
            s += e[c];
        }
        for (int c = 0; c < DK; c++)
            shifts[base + c] = (int)(e[c] / s);
    }
}

// =============================== launch =======================================
extern "C" void kernel_launch(void* const* d_in, const int* in_sizes, int n_in,
                              void* d_out, int out_size)
{
    const float* q  = (const float*)d_in[0];
    const float* k  = (const float*)d_in[1];
    const float* v  = (const float*)d_in[2];
    const float* Wq = (const float*)d_in[3];
    const float* bq = (const float*)d_in[4];
    const float* Wk = (const float*)d_in[5];
    const float* bk = (const float*)d_in[6];
    const float* Wv = (const float*)d_in[7];
    const float* bv = (const float*)d_in[8];
    const float* Wo = (const float*)d_in[9];
    const float* bo = (const float*)d_in[10];
    float* out = (float*)d_out;

    float *qp, *kp, *vp, *Mf;
    double* Md;
    int *sh, *fl;
    __nv_bfloat16 *Ah, *Al, *WhT, *WlT;
    cudaGetSymbolAddress((void**)&qp, g_qp);
    cudaGetSymbolAddress((void**)&kp, g_kp);
    cudaGetSymbolAddress((void**)&vp, g_vp);
    cudaGetSymbolAddress((void**)&Mf, g_Mf);
    cudaGetSymbolAddress((void**)&Md, g_Md);
    cudaGetSymbolAddress((void**)&sh, g_shift);
    cudaGetSymbolAddress((void**)&fl, g_flag);
    cudaGetSymbolAddress((void**)&Ah, g_Ah);
    cudaGetSymbolAddress((void**)&Al, g_Al);
    cudaGetSymbolAddress((void**)&WhT, g_WhT);
    cudaGetSymbolAddress((void**)&WlT, g_WlT);

    const size_t ASLOT = (size_t)MTOT * DD;
    const size_t WSLOT = (size_t)DD * DD;

    // one-time host-side stream/event setup (first call is the harness's
    // correctness run, outside graph capture; per-call captured work is
    // identical every call)
    static cudaStream_t s_side = nullptr;
    static cudaEvent_t ev_w = nullptr, ev_join = nullptr;
    if (s_side == nullptr) {
        cudaStreamCreateWithFlags(&s_side, cudaStreamNonBlocking);
        cudaEventCreateWithFlags(&ev_w, cudaEventDisableTiming);
        cudaEventCreateWithFlags(&ev_join, cudaEventDisableTiming);
    }

    cudaFuncSetAttribute(gemm_mma_kernel,
                         cudaFuncAttributeMaxDynamicSharedMemorySize, GSMEM_TOTAL);
    cudaFuncSetAttribute(autocorr_f32_kernel,
                         cudaFuncAttributeMaxDynamicSharedMemorySize, AC_SMEM_F);
    cudaFuncSetAttribute(autocorr_dp_kernel,
                         cudaFuncAttributeMaxDynamicSharedMemorySize, AC_SMEM_D);

    twiddle_init_kernel<<<4, 256>>>();

    // weight transpose+splits (all four) on main stream, then fork point
    ConvW4 cw;
    cw.W[0] = Wq; cw.W[1] = Wk; cw.W[2] = Wv; cw.W[3] = Wo;
    for (int z = 0; z < 4; z++) { cw.h[z] = WhT + z * WSLOT; cw.l[z] = WlT + z * WSLOT; }
    convWT4_kernel<<<dim3(32, 32, 4), dim3(32, 8)>>>(cw);
    cudaEventRecord(ev_w, 0);

    // ---- side stream: V chain (conv v + V-GEMM), independent of Q/K ----
    cudaStreamWaitEvent(s_side, ev_w, 0);
    ConvA3 cv;
    cv.src[0] = (const float4*)v;
    cv.h[0] = (__nv_bfloat162*)(Ah + 2 * ASLOT);
    cv.l[0] = (__nv_bfloat162*)(Al + 2 * ASLOT);
    cv.src[1] = cv.src[0]; cv.h[1] = cv.h[0]; cv.l[1] = cv.l[0];
    cv.src[2] = cv.src[0]; cv.h[2] = cv.h[0]; cv.l[2] = cv.l[0];
    convA3_kernel<<<dim3((MTOT * DD / 4) / 256, 1, 1), 256, 0, s_side>>>(cv);
    GemmArgs3 gV = {};
    gV.g[0] = { Ah + 2 * ASLOT, Al + 2 * ASLOT, WhT + 2 * WSLOT, WlT + 2 * WSLOT,
                bv, vp, DD, 0 };
    gV.g[1] = gV.g[0];
    gV.g[2] = gV.g[0];
    gemm_mma_kernel<<<dim3(64, 8, 1), 256, GSMEM_TOTAL, s_side>>>(gV);
    cudaEventRecord(ev_join, s_side);

    // ---- main stream: Q/K conv + QK-GEMM + autocorr chain ----
    ConvA3 ca;
    ca.src[0] = (const float4*)q; ca.src[1] = (const float4*)k;
    ca.h[0] = (__nv_bfloat162*)(Ah + 0 * ASLOT);
    ca.l[0] = (__nv_bfloat162*)(Al + 0 * ASLOT);
    ca.h[1] = (__nv_bfloat162*)(Ah + 1 * ASLOT);
    ca.l[1] = (__nv_bfloat162*)(Al + 1 * ASLOT);
    ca.src[2] = ca.src[0]; ca.h[2] = ca.h[0]; ca.l[2] = ca.l[0];
    convA3_kernel<<<dim3((MTOT * DD / 4) / 256, 1, 2), 256>>>(ca);

    GemmArgs3 gQK = {};
    gQK.g[0] = { WhT + 0 * WSLOT, WlT + 0 * WSLOT, Ah + 0 * ASLOT, Al + 0 * ASLOT,
                 bq, qp, MTOT, 1 };
    gQK.g[1] = { WhT + 1 * WSLOT, WlT + 1 * WSLOT, Ah + 1 * ASLOT, Al + 1 * ASLOT,
                 bk, kp, MTOT, 1 };
    gQK.g[2] = gQK.g[0];
    gemm_mma_kernel<<<dim3(64, 8, 2), 256, GSMEM_TOTAL>>>(gQK);

    autocorr_f32_kernel<<<BB * DD / 2, AC_T, AC_SMEM_F>>>(qp, kp, Mf);
    flag_softmax_kernel<<<BB * HH, 32>>>(Mf, sh, fl);
    autocorr_dp_kernel<<<BB * DD / 2, AC_T, AC_SMEM_D>>>(qp, kp, fl, Md);
    softmax_fix_kernel<<<BB * HH, 32>>>(Md, fl, sh);

    // join: need vp (side) + shifts (main)
    cudaStreamWaitEvent(0, ev_join, 0);
    convA_shift_kernel<<<(MTOT * DD / 4) / 256, 256>>>(vp, sh,
        (__nv_bfloat162*)(Ah + 0 * ASLOT), (__nv_bfloat162*)(Al + 0 * ASLOT));

    // output projection
    GemmArgs3 gO = {};
    gO.g[0] = { Ah + 0 * ASLOT, Al + 0 * ASLOT, WhT + 3 * WSLOT, WlT + 3 * WSLOT,
                bo, out, DD, 0 };
    gO.g[1] = gO.g[0];
    gO.g[2] = gO.g[0];
    gemm_mma_kernel<<<dim3(64, 8, 1), 256, GSMEM_TOTAL>>>(gO);
}

// round 16
// speedup vs baseline: 1.0480x; 1.0480x over previous
#include <cuda_runtime.h>
#include <cuda_bf16.h>
#include <cstdint>
#include <math.h>

// Problem constants
#define BB 4
#define LL 2048
#define DD 1024
#define HH 16
#define DK 64
#define MTOT (BB*LL)          // 8192

// ---------------- scratch (device globals; no allocation allowed) ------------
__device__ float  g_qp[BB*LL*DD];     // qpT [1024, 8192]
__device__ float  g_kp[BB*LL*DD];     // kpT [1024, 8192]
__device__ float  g_vp[BB*LL*DD];     // vp natural [8192, 1024]
__device__ float  g_Mf[BB*DD];        // fp32 per-channel max autocorr
__device__ double g_Md[BB*DD];        // DP rescue values (flagged heads only)
__device__ int    g_flag[BB*HH];      // per-head "borderline" flag
__device__ int    g_shift[BB*DD];
__device__ double2 g_tw[1024];        // DP twiddles exp(-2*pi*i*j/2048)
__device__ float2  g_twf[1024];       // fp32 twiddles
// bf16 split scratch: 3 activation slots, 4 weight slots
__device__ __nv_bfloat16 g_Ah[3ULL*MTOT*DD];
__device__ __nv_bfloat16 g_Al[3ULL*MTOT*DD];
__device__ __nv_bfloat16 g_WhT[4ULL*DD*DD];
__device__ __nv_bfloat16 g_WlT[4ULL*DD*DD];

// ============================ PTX helpers =====================================
__device__ __forceinline__ uint32_t smem_u32(const void* p) {
    uint32_t a;
    asm("{ .reg .u64 t; cvta.to.shared.u64 t, %1; cvt.u32.u64 %0, t; }"
        : "=r"(a) : "l"(p));
    return a;
}
__device__ __forceinline__ void cp16(uint32_t dst, const void* src) {
    asm volatile("cp.async.cg.shared.global [%0], [%1], 16;\n" :: "r"(dst), "l"(src));
}
#define CP_COMMIT() asm volatile("cp.async.commit_group;" ::: "memory")

__device__ __forceinline__ void ldsm4(uint32_t (&r)[4], uint32_t addr) {
    asm volatile("ldmatrix.sync.aligned.m8n8.x4.shared.b16 {%0,%1,%2,%3}, [%4];"
        : "=r"(r[0]), "=r"(r[1]), "=r"(r[2]), "=r"(r[3]) : "r"(addr));
}
__device__ __forceinline__ void mma_bf16(float (&d)[4], const uint32_t (&a)[4],
                                         uint32_t b0, uint32_t b1) {
    asm volatile("mma.sync.aligned.m16n8k16.row.col.f32.bf16.bf16.f32 "
        "{%0,%1,%2,%3}, {%4,%5,%6,%7}, {%8,%9}, {%0,%1,%2,%3};"
        : "+f"(d[0]), "+f"(d[1]), "+f"(d[2]), "+f"(d[3])
        : "r"(a[0]), "r"(a[1]), "r"(a[2]), "r"(a[3]), "r"(b0), "r"(b1));
}

// ==================== mma.sync bf16-split GEMM (batched) ======================
#define BK 32
#define NKITER (DD / BK)      // 32
#define SMAT (128 * 64)       // 8192 bytes per matrix tile
#define SSTAGE (4 * SMAT)     // 32768
#define NSTAGE 3
#define GSMEM_TOTAL (NSTAGE * SSTAGE)   // 98304

#define SWZ(r, c) ((c) ^ ((r) & 3) ^ (((r) >> 2) & 1))

struct GemmArgs {
    const __nv_bfloat16 *Ah, *Al, *Bh, *Bl;
    const float* bias;
    float* C;
    int cstride;
    int rowbias;   // 1: T-orientation (m0 from blockIdx.y, bias[m]); 0: normal
};
struct GemmArgs3 { GemmArgs g[3]; };

__global__ __launch_bounds__(256) void gemm_mma_kernel(GemmArgs3 args)
{
    const GemmArgs a = args.g[blockIdx.z];
    extern __shared__ __align__(128) char smem[];
    const uint32_t sb = smem_u32(smem);
    const int tid = threadIdx.x;
    const int wid = tid >> 5;
    const int lane = tid & 31;
    const int m0 = (a.rowbias ? blockIdx.y : blockIdx.x) << 7;
    const int n0 = (a.rowbias ? blockIdx.x : blockIdx.y) << 7;
    const int mw = (wid >> 2) << 6;
    const int nw = (wid & 3) << 5;

    float acc[4][4][4];
    #pragma unroll
    for (int mt = 0; mt < 4; mt++)
        #pragma unroll
        for (int nt = 0; nt < 4; nt++)
            #pragma unroll
            for (int e = 0; e < 4; e++) acc[mt][nt][e] = 0.f;

    auto issue = [&](int kb, int s) {
        const uint32_t base = sb + s * SSTAGE;
        const int k0 = kb * BK;
        #pragma unroll
        for (int i = 0; i < 2; i++) {
            int e = tid + (i << 8);
            int r = e >> 2;
            int c = e & 3;
            uint32_t doff = (uint32_t)(r * 64 + SWZ(r, c) * 16);
            const char* pa = (const char*)(a.Ah + (size_t)(m0 + r) * DD + k0) + c * 16;
            const char* pl = (const char*)(a.Al + (size_t)(m0 + r) * DD + k0) + c * 16;
            const char* pb = (const char*)(a.Bh + (size_t)(n0 + r) * DD + k0) + c * 16;
            const char* pq = (const char*)(a.Bl + (size_t)(n0 + r) * DD + k0) + c * 16;
            cp16(base + 0 * SMAT + doff, pa);
            cp16(base + 1 * SMAT + doff, pl);
            cp16(base + 2 * SMAT + doff, pb);
            cp16(base + 3 * SMAT + doff, pq);
        }
        CP_COMMIT();
    };

    issue(0, 0);
    issue(1, 1);

    for (int kb = 0; kb < NKITER; kb++) {
        if (kb == NKITER - 1) asm volatile("cp.async.wait_group 0;" ::: "memory");
        else                  asm volatile("cp.async.wait_group 1;" ::: "memory");
        __syncthreads();
        if (kb + 2 < NKITER) issue(kb + 2, (kb + 2) % NSTAGE);

        const uint32_t base = sb + (kb % NSTAGE) * SSTAGE;
        #pragma unroll
        for (int ks = 0; ks < 2; ks++) {
            uint32_t ah[4][4], al[4][4];
            #pragma unroll
            for (int mt = 0; mt < 4; mt++) {
                int row = mw + (mt << 4) + (lane & 15);
                int cc = ks * 2 + (lane >> 4);
                uint32_t addr = base + (uint32_t)(row * 64 + SWZ(row, cc) * 16);
                ldsm4(ah[mt], addr);
                ldsm4(al[mt], addr + SMAT);
            }
            uint32_t bh[2][4], bl[2][4];
            #pragma unroll
            for (int p = 0; p < 2; p++) {
                int nrow = nw + (p << 4) + (lane & 7) + (((lane >> 4) & 1) << 3);
                int cc = ks * 2 + ((lane >> 3) & 1);
                uint32_t addr = base + 2 * SMAT
                              + (uint32_t)(nrow * 64 + SWZ(nrow, cc) * 16);
                ldsm4(bh[p], addr);
                ldsm4(bl[p], addr + SMAT);
            }
            #pragma unroll
            for (int mt = 0; mt < 4; mt++)
                #pragma unroll
                for (int nt = 0; nt < 4; nt++) {
                    uint32_t h0 = bh[nt >> 1][(nt & 1) * 2];
                    uint32_t h1 = bh[nt >> 1][(nt & 1) * 2 + 1];
                    uint32_t l0 = bl[nt >> 1][(nt & 1) * 2];
                    uint32_t l1 = bl[nt >> 1][(nt & 1) * 2 + 1];
                    mma_bf16(acc[mt][nt], ah[mt], h0, h1);
                    mma_bf16(acc[mt][nt], ah[mt], l0, l1);
                    mma_bf16(acc[mt][nt], al[mt], h0, h1);
                }
        }
    }

    #pragma unroll
    for (int mt = 0; mt < 4; mt++) {
        #pragma unroll
        for (int nt = 0; nt < 4; nt++) {
            int m = m0 + mw + (mt << 4) + (lane >> 2);
            int n = n0 + nw + (nt << 3) + ((lane & 3) << 1);
            float2 v0, v1;
            if (a.rowbias) {
                float bm0 = a.bias[m], bm1 = a.bias[m + 8];
                v0 = make_float2(acc[mt][nt][0] + bm0, acc[mt][nt][1] + bm0);
                v1 = make_float2(acc[mt][nt][2] + bm1, acc[mt][nt][3] + bm1);
            } else {
                float b0 = a.bias[n], b1 = a.bias[n + 1];
                v0 = make_float2(acc[mt][nt][0] + b0, acc[mt][nt][1] + b1);
                v1 = make_float2(acc[mt][nt][2] + b0, acc[mt][nt][3] + b1);
            }
            *(float2*)(a.C + (size_t)m * a.cstride + n) = v0;
            *(float2*)(a.C + (size_t)(m + 8) * a.cstride + n) = v1;
        }
    }
}

// ==================== fp32 -> bf16 hi/lo converters (batched) =================
// 8 elements per thread, 16-byte stores for hi and lo.
struct ConvA3 {
    const float4* src[3];
    __nv_bfloat162* h[3];
    __nv_bfloat162* l[3];
};
__global__ void convA3_kernel(ConvA3 p)
{
    const int z = blockIdx.z;
    int i = blockIdx.x * blockDim.x + threadIdx.x;   // over MTOT*DD/8
    float4 v0 = p.src[z][2 * i + 0];
    float4 v1 = p.src[z][2 * i + 1];
    float f[8] = {v0.x, v0.y, v0.z, v0.w, v1.x, v1.y, v1.z, v1.w};
    __nv_bfloat162 hh[4], ll[4];
    #pragma unroll
    for (int j = 0; j < 4; j++) {
        __nv_bfloat16 a = __float2bfloat16(f[2 * j]);
        __nv_bfloat16 b = __float2bfloat16(f[2 * j + 1]);
        hh[j] = __halves2bfloat162(a, b);
        ll[j] = __halves2bfloat162(
            __float2bfloat16(f[2 * j] - __bfloat162float(a)),
            __float2bfloat16(f[2 * j + 1] - __bfloat162float(b)));
    }
    ((uint4*)p.h[z])[i] = *(uint4*)hh;
    ((uint4*)p.l[z])[i] = *(uint4*)ll;
}

// fused: roll vp by per-(b,c) shift (0/1) while converting to bf16 hi/lo
__global__ void convA_shift_kernel(const float* __restrict__ vp,
                                   const int* __restrict__ shifts,
                                   __nv_bfloat162* __restrict__ Ah2,
                                   __nv_bfloat162* __restrict__ Al2)
{
    int i = blockIdx.x * blockDim.x + threadIdx.x;
    int c4 = (i & 255) << 2;
    int t = (i >> 8) & 2047;
    int b = i >> 19;
    const int sbase = (b << 10) + c4;
    float v[4];
    #pragma unroll
    for (int j = 0; j < 4; j++) {
        int s = shifts[sbase + j];
        int t2 = (t - s) & 2047;
        v[j] = vp[((size_t)((b << 11) + t2) << 10) + c4 + j];
    }
    __nv_bfloat16 h0 = __float2bfloat16(v[0]);
    __nv_bfloat16 h1 = __float2bfloat16(v[1]);
    __nv_bfloat16 h2 = __float2bfloat16(v[2]);
    __nv_bfloat16 h3 = __float2bfloat16(v[3]);
    Ah2[2 * i + 0] = __halves2bfloat162(h0, h1);
    Ah2[2 * i + 1] = __halves2bfloat162(h2, h3);
    Al2[2 * i + 0] = __halves2bfloat162(
        __float2bfloat16(v[0] - __bfloat162float(h0)),
        __float2bfloat16(v[1] - __bfloat162float(h1)));
    Al2[2 * i + 1] = __halves2bfloat162(
        __float2bfloat16(v[2] - __bfloat162float(h2)),
        __float2bfloat16(v[3] - __bfloat162float(h3)));
}

struct ConvW4 {
    const float* W[4];
    __nv_bfloat16* h[4];
    __nv_bfloat16* l[4];
};
__global__ void convWT4_kernel(ConvW4 p)
{
    __shared__ float t[32][33];
    const int z = blockIdx.z;
    const int tx = threadIdx.x, ty = threadIdx.y;
    const int kb = blockIdx.y * 32, nb = blockIdx.x * 32;
    #pragma unroll
    for (int j = 0; j < 32; j += 8)
        t[ty + j][tx] = p.W[z][(size_t)(kb + ty + j) * DD + nb + tx];
    __syncthreads();
    #pragma unroll
    for (int j = 0; j < 32; j += 8) {
        float v = t[tx][ty + j];
        __nv_bfloat16 h = __float2bfloat16(v);
        p.h[z][(size_t)(nb + ty + j) * DD + kb + tx] = h;
        p.l[z][(size_t)(nb + ty + j) * DD + kb + tx] =
            __float2bfloat16(v - __bfloat162float(h));
    }
}

// ======================= twiddle init (DP + fp32) =============================
__global__ void twiddle_init_kernel() {
    int j = blockIdx.x * blockDim.x + threadIdx.x;
    if (j < 1024) {
        double ang = -6.283185307179586476925286766559 * (double)j / 2048.0;
        double s, c;
        sincos(ang, &s, &c);
        g_tw[j] = make_double2(c, s);
        g_twf[j] = make_float2((float)c, (float)s);
    }
}

// ===== Stockham DIF FFT autocorrelation (fp32 fast path + DP rescue) ==========
#define FFT_N 2048
#define AC_T 256
#define AC_SMEM_D (3 * FFT_N * 16)   // 98304 bytes (DP)
#define AC_SMEM_F (3 * FFT_N * 8)    // 49152 bytes (fp32)

__device__ __forceinline__ double2* fft11d(double2* x, double2* y, int tid) {
    double2* src = x;
    double2* dst = y;
    #pragma unroll
    for (int t = 0; t < 11; t++) {
        const int s = 1 << t;
        for (int j = tid; j < FFT_N / 2; j += AC_T) {
            int q = j & (s - 1);
            int ps = (j >> t) << t;
            double2 a = src[q + ps];
            double2 b = src[q + ps + FFT_N / 2];
            double2 w = g_tw[ps];
            double sx = a.x - b.x, sy = a.y - b.y;
            dst[q + 2 * ps]     = make_double2(a.x + b.x, a.y + b.y);
            dst[q + 2 * ps + s] = make_double2(sx * w.x - sy * w.y,
                                               sx * w.y + sy * w.x);
        }
        __syncthreads();
        double2* tmp = src; src = dst; dst = tmp;
    }
    return src;
}

__device__ __forceinline__ float2* fft11f(float2* x, float2* y, int tid) {
    float2* src = x;
    float2* dst = y;
    #pragma unroll
    for (int t = 0; t < 11; t++) {
        const int s = 1 << t;
        for (int j = tid; j < FFT_N / 2; j += AC_T) {
            int q = j & (s - 1);
            int ps = (j >> t) << t;
            float2 a = src[q + ps];
            float2 b = src[q + ps + FFT_N / 2];
            float2 w = g_twf[ps];
            float sx = a.x - b.x, sy = a.y - b.y;
            dst[q + 2 * ps]     = make_float2(a.x + b.x, a.y + b.y);
            dst[q + 2 * ps + s] = make_float2(sx * w.x - sy * w.y,
                                              sx * w.y + sy * w.x);
        }
        __syncthreads();
        float2* tmp = src; src = dst; dst = tmp;
    }
    return src;
}

__global__ __launch_bounds__(AC_T) void autocorr_f32_kernel(
    const float* __restrict__ qpT, const float* __restrict__ kpT,
    float* __restrict__ Mout)
{
    extern __shared__ float2 sbf[];
    float2* B0 = sbf;
    float2* B1 = sbf + FFT_N;
    float2* BC = sbf + 2 * FFT_N;
    __shared__ float red[16];

    const int tid = threadIdx.x;
    const int ch0 = blockIdx.x * 2;
    const int ch1 = ch0 + 1;
    const size_t a0 = (size_t)(ch0 & 1023) * 8192 + (size_t)(ch0 >> 10) * 2048;
    const size_t a1 = (size_t)(ch1 & 1023) * 8192 + (size_t)(ch1 >> 10) * 2048;

    for (int i = tid; i < FFT_N; i += AC_T)
        B0[i] = make_float2(qpT[a0 + i], kpT[a0 + i]);
    __syncthreads();
    float2* Z = fft11f(B0, B1, tid);

    for (int f = tid; f <= FFT_N / 2; f += AC_T) {
        int f2 = (FFT_N - f) & (FFT_N - 1);
        float2 z1 = Z[f];
        float2 z2 = Z[f2];
        float2 fq = make_float2(0.5f * (z1.x + z2.x), 0.5f * (z1.y - z2.y));
        float2 fk = make_float2(0.5f * (z1.y + z2.y), -0.5f * (z1.x - z2.x));
        float gx = fq.x * fk.x + fq.y * fk.y;
        float gy = fq.y * fk.x - fq.x * fk.y;
        BC[f]  = make_float2(gx, -gy);
        BC[f2] = make_float2(gx,  gy);
    }
    for (int i = tid; i < FFT_N; i += AC_T)
        B0[i] = make_float2(qpT[a1 + i], kpT[a1 + i]);
    __syncthreads();
    Z = fft11f(B0, B1, tid);

    for (int f = tid; f <= FFT_N / 2; f += AC_T) {
        int f2 = (FFT_N - f) & (FFT_N - 1);
        float2 z1 = Z[f];
        float2 z2 = Z[f2];
        float2 fq = make_float2(0.5f * (z1.x + z2.x), 0.5f * (z1.y - z2.y));
        float2 fk = make_float2(0.5f * (z1.y + z2.y), -0.5f * (z1.x - z2.x));
        float gx = fq.x * fk.x + fq.y * fk.y;
        float gy = fq.y * fk.x - fq.x * fk.y;
        float2 c0 = BC[f];
        float2 c2 = BC[f2];
        B0[f]  = make_float2(c0.x - gy, c0.y - gx);
        B0[f2] = make_float2(c2.x + gy, c2.y - gx);
    }
    __syncthreads();
    float2* Y = fft11f(B0, B1, tid);

    float m0 = -3.0e38f, m1 = -3.0e38f;
    for (int i = tid; i < FFT_N; i += AC_T) {
        if (i != 0) {
            float2 y = Y[i];
            m0 = fmaxf(m0, y.x);
            m1 = fmaxf(m1, -y.y);
        }
    }
    #pragma unroll
    for (int off = 16; off > 0; off >>= 1) {
        m0 = fmaxf(m0, __shfl_xor_sync(0xffffffffu, m0, off));
        m1 = fmaxf(m1, __shfl_xor_sync(0xffffffffu, m1, off));
    }
    if ((tid & 31) == 0) { red[tid >> 5] = m0; red[8 + (tid >> 5)] = m1; }
    __syncthreads();
    if (tid == 0) {
        float r0 = red[0], r1 = red[8];
        #pragma unroll
        for (int w = 1; w < AC_T / 32; w++) {
            r0 = fmaxf(r0, red[w]);
            r1 = fmaxf(r1, red[8 + w]);
        }
        Mout[ch0] = r0 * (1.0f / FFT_N);
        Mout[ch1] = r1 * (1.0f / FFT_N);
    }
}

__global__ __launch_bounds__(AC_T) void autocorr_dp_kernel(
    const float* __restrict__ qpT, const float* __restrict__ kpT,
    const int* __restrict__ flag, double* __restrict__ Mout)
{
    const int ch0 = blockIdx.x * 2;
    if (flag[ch0 >> 6] == 0) return;

    extern __shared__ double2 sbd[];
    double2* B0 = sbd;
    double2* B1 = sbd + FFT_N;
    double2* BC = sbd + 2 * FFT_N;
    __shared__ double red[16];

    const int tid = threadIdx.x;
    const int ch1 = ch0 + 1;
    const size_t a0 = (size_t)(ch0 & 1023) * 8192 + (size_t)(ch0 >> 10) * 2048;
    const size_t a1 = (size_t)(ch1 & 1023) * 8192 + (size_t)(ch1 >> 10) * 2048;

    for (int i = tid; i < FFT_N; i += AC_T)
        B0[i] = make_double2((double)qpT[a0 + i], (double)kpT[a0 + i]);
    __syncthreads();
    double2* Z = fft11d(B0, B1, tid);

    for (int f = tid; f <= FFT_N / 2; f += AC_T) {
        int f2 = (FFT_N - f) & (FFT_N - 1);
        double2 z1 = Z[f];
        double2 z2 = Z[f2];
        double2 fq = make_double2(0.5 * (z1.x + z2.x), 0.5 * (z1.y - z2.y));
        double2 fk = make_double2(0.5 * (z1.y + z2.y), -0.5 * (z1.x - z2.x));
        double gx = fq.x * fk.x + fq.y * fk.y;
        double gy = fq.y * fk.x - fq.x * fk.y;
        BC[f]  = make_double2(gx, -gy);
        BC[f2] = make_double2(gx,  gy);
    }
    for (int i = tid; i < FFT_N; i += AC_T)
        B0[i] = make_double2((double)qpT[a1 + i], (double)kpT[a1 + i]);
    __syncthreads();
    Z = fft11d(B0, B1, tid);

    for (int f = tid; f <= FFT_N / 2; f += AC_T) {
        int f2 = (FFT_N - f) & (FFT_N - 1);
        double2 z1 = Z[f];
        double2 z2 = Z[f2];
        double2 fq = make_double2(0.5 * (z1.x + z2.x), 0.5 * (z1.y - z2.y));
        double2 fk = make_double2(0.5 * (z1.y + z2.y), -0.5 * (z1.x - z2.x));
        double gx = fq.x * fk.x + fq.y * fk.y;
        double gy = fq.y * fk.x - fq.x * fk.y;
        double2 c0 = BC[f];
        double2 c2 = BC[f2];
        B0[f]  = make_double2(c0.x - gy, c0.y - gx);
        B0[f2] = make_double2(c2.x + gy, c2.y - gx);
    }
    __syncthreads();
    double2* Y = fft11d(B0, B1, tid);

    double m0 = -1.0e300, m1 = -1.0e300;
    for (int i = tid; i < FFT_N; i += AC_T) {
        if (i != 0) {
            double2 y = Y[i];
            m0 = fmax(m0, y.x);
            m1 = fmax(m1, -y.y);
        }
    }
    #pragma unroll
    for (int off = 16; off > 0; off >>= 1) {
        m0 = fmax(m0, __shfl_xor_sync(0xffffffffu, m0, off));
        m1 = fmax(m1, __shfl_xor_sync(0xffffffffu, m1, off));
    }
    if ((tid & 31) == 0) { red[tid >> 5] = m0; red[8 + (tid >> 5)] = m1; }
    __syncthreads();
    if (tid == 0) {
        double r0 = red[0], r1 = red[8];
        #pragma unroll
        for (int w = 1; w < AC_T / 32; w++) {
            r0 = fmax(r0, red[w]);
            r1 = fmax(r1, red[8 + w]);
        }
        Mout[ch0] = r0 * (1.0 / FFT_N);
        Mout[ch1] = r1 * (1.0 / FFT_N);
    }
}

// ===== per-head fp32 softmax + shifts + borderline flag =======================
__global__ void flag_softmax_kernel(const float* __restrict__ Mf,
                                    int* __restrict__ shifts,
                                    int* __restrict__ flag)
{
    const int bh = blockIdx.x;
    const int base = ((bh >> 4) << 10) + ((bh & 15) << 6);
    if (threadIdx.x == 0) {
        float x[DK];
        float mx = -3.4e38f;
        int amax = 0;
        for (int c = 0; c < DK; c++) {
            x[c] = Mf[base + c];
            if (x[c] > mx) { mx = x[c]; amax = c; }
        }
        float e[DK];
        float s = 0.f;
        for (int c = 0; c < DK; c++) {
            e[c] = expf(x[c] - mx);
            s += e[c];
        }
        for (int c = 0; c < DK; c++)
            shifts[base + c] = (int)(e[c] / s);
        double rest = 0.0;
        for (int c = 0; c < DK; c++)
            if (c != amax) rest += exp((double)x[c] - (double)mx);
        double l2 = log2(rest);
        flag[bh] = (fabs(l2 + 24.0) < 0.5) ? 1 : 0;
    }
}

__global__ void softmax_fix_kernel(const double* __restrict__ Md,
                                   const int* __restrict__ flag,
                                   int* __restrict__ shifts)
{
    const int bh = blockIdx.x;
    if (flag[bh] == 0) return;
    const int base = ((bh >> 4) << 10) + ((bh & 15) << 6);
    if (threadIdx.x == 0) {
        float x[DK];
        float mx = -3.4e38f;
        for (int c = 0; c < DK; c++) {
            x[c] = (float)Md[base + c];
            mx = fmaxf(mx, x[c]);
        }
        float e[DK];
        float s = 0.f;
        for (int c = 0; c < DK; c++) {
            e[c] = expf(x[c] - mx);
            s += e[c];
        }
        for (int c = 0; c < DK; c++)
            shifts[base + c] = (int)(e[c] / s);
    }
}

// =============================== launch =======================================
extern "C" void kernel_launch(void* const* d_in, const int* in_sizes, int n_in,
                              void* d_out, int out_size)
{
    const float* q  = (const float*)d_in[0];
    const float* k  = (const float*)d_in[1];
    const float* v  = (const float*)d_in[2];
    const float* Wq = (const float*)d_in[3];
    const float* bq = (const float*)d_in[4];
    const float* Wk = (const float*)d_in[5];
    const float* bk = (const float*)d_in[6];
    const float* Wv = (const float*)d_in[7];
    const float* bv = (const float*)d_in[8];
    const float* Wo = (const float*)d_in[9];
    const float* bo = (const float*)d_in[10];
    float* out = (float*)d_out;

    float *qp, *kp, *vp, *Mf;
    double* Md;
    int *sh, *fl;
    __nv_bfloat16 *Ah, *Al, *WhT, *WlT;
    cudaGetSymbolAddress((void**)&qp, g_qp);
    cudaGetSymbolAddress((void**)&kp, g_kp);
    cudaGetSymbolAddress((void**)&vp, g_vp);
    cudaGetSymbolAddress((void**)&Mf, g_Mf);
    cudaGetSymbolAddress((void**)&Md, g_Md);
    cudaGetSymbolAddress((void**)&sh, g_shift);
    cudaGetSymbolAddress((void**)&fl, g_flag);
    cudaGetSymbolAddress((void**)&Ah, g_Ah);
    cudaGetSymbolAddress((void**)&Al, g_Al);
    cudaGetSymbolAddress((void**)&WhT, g_WhT);
    cudaGetSymbolAddress((void**)&WlT, g_WlT);

    const size_t ASLOT = (size_t)MTOT * DD;
    const size_t WSLOT = (size_t)DD * DD;

    // one-time host-side stream/event setup (first call is the harness's
    // correctness run, outside graph capture; per-call captured work is
    // identical every call)
    static cudaStream_t s_side = nullptr;
    static cudaEvent_t ev_fork = nullptr, ev_join = nullptr;
    if (s_side == nullptr) {
        cudaStreamCreateWithFlags(&s_side, cudaStreamNonBlocking);
        cudaEventCreateWithFlags(&ev_fork, cudaEventDisableTiming);
        cudaEventCreateWithFlags(&ev_join, cudaEventDisableTiming);
    }

    cudaFuncSetAttribute(gemm_mma_kernel,
                         cudaFuncAttributeMaxDynamicSharedMemorySize, GSMEM_TOTAL);
    cudaFuncSetAttribute(autocorr_f32_kernel,
                         cudaFuncAttributeMaxDynamicSharedMemorySize, AC_SMEM_F);
    cudaFuncSetAttribute(autocorr_dp_kernel,
                         cudaFuncAttributeMaxDynamicSharedMemorySize, AC_SMEM_D);

    twiddle_init_kernel<<<4, 256>>>();

    ConvW4 cw;
    cw.W[0] = Wq; cw.W[1] = Wk; cw.W[2] = Wv; cw.W[3] = Wo;
    for (int z = 0; z < 4; z++) { cw.h[z] = WhT + z * WSLOT; cw.l[z] = WlT + z * WSLOT; }
    convWT4_kernel<<<dim3(32, 32, 4), dim3(32, 8)>>>(cw);

    ConvA3 ca;
    ca.src[0] = (const float4*)q; ca.src[1] = (const float4*)k; ca.src[2] = (const float4*)v;
    for (int z = 0; z < 3; z++) {
        ca.h[z] = (__nv_bfloat162*)(Ah + z * ASLOT);
        ca.l[z] = (__nv_bfloat162*)(Al + z * ASLOT);
    }
    convA3_kernel<<<dim3((MTOT * DD / 8) / 256, 1, 3), 256>>>(ca);

    // Q,K projections (transposed orientation) in one batched launch
    GemmArgs3 gQK = {};
    gQK.g[0] = { WhT + 0 * WSLOT, WlT + 0 * WSLOT, Ah + 0 * ASLOT, Al + 0 * ASLOT,
                 bq, qp, MTOT, 1 };
    gQK.g[1] = { WhT + 1 * WSLOT, WlT + 1 * WSLOT, Ah + 1 * ASLOT, Al + 1 * ASLOT,
                 bk, kp, MTOT, 1 };
    gQK.g[2] = gQK.g[0];
    gemm_mma_kernel<<<dim3(64, 8, 2), 256, GSMEM_TOTAL>>>(gQK);

    // fork: V projection (independent of autocorr chain) on side stream
    cudaEventRecord(ev_fork, 0);
    cudaStreamWaitEvent(s_side, ev_fork, 0);
    GemmArgs3 gV = {};
    gV.g[0] = { Ah + 2 * ASLOT, Al + 2 * ASLOT, WhT + 2 * WSLOT, WlT + 2 * WSLOT,
                bv, vp, DD, 0 };
    gV.g[1] = gV.g[0];
    gV.g[2] = gV.g[0];
    gemm_mma_kernel<<<dim3(64, 8, 1), 256, GSMEM_TOTAL, s_side>>>(gV);
    cudaEventRecord(ev_join, s_side);

    // main stream: autocorrelation chain, concurrent with V-GEMM
    autocorr_f32_kernel<<<BB * DD / 2, AC_T, AC_SMEM_F>>>(qp, kp, Mf);
    flag_softmax_kernel<<<BB * HH, 32>>>(Mf, sh, fl);
    autocorr_dp_kernel<<<BB * DD / 2, AC_T, AC_SMEM_D>>>(qp, kp, fl, Md);
    softmax_fix_kernel<<<BB * HH, 32>>>(Md, fl, sh);

    // join: need vp (side) + shifts (main)
    cudaStreamWaitEvent(0, ev_join, 0);
    convA_shift_kernel<<<(MTOT * DD / 4) / 256, 256>>>(vp, sh,
        (__nv_bfloat162*)(Ah + 0 * ASLOT), (__nv_bfloat162*)(Al + 0 * ASLOT));

    // output projection
    GemmArgs3 gO = {};
    gO.g[0] = { Ah + 0 * ASLOT, Al + 0 * ASLOT, WhT + 3 * WSLOT, WlT + 3 * WSLOT,
                bo, out, DD, 0 };
    gO.g[1] = gO.g[0];
    gO.g[2] = gO.g[0];
    gemm_mma_kernel<<<dim3(64, 8, 1), 256, GSMEM_TOTAL>>>(gO);
}